// round 2
// baseline (speedup 1.0000x reference)
#include <cuda_runtime.h>

#define R_RUNS 128
#define T_STEPS 1024
#define N_AGENTS 128
#define NT 64      // threads per block = N_AGENTS/2
#define PF 4       // prefetch depth (phases ahead)
#define NPHASE 1087

typedef unsigned long long u64;

__device__ __forceinline__ float ex2_approx(float x) {
    float r;
    asm("ex2.approx.f32 %0, %1;" : "=f"(r) : "f"(x));
    return r;
}
__device__ __forceinline__ float rcp_approx(float x) {
    float r;
    asm("rcp.approx.f32 %0, %1;" : "=f"(r) : "f"(x));
    return r;
}
__device__ __forceinline__ u64 pk(float lo, float hi) {
    u64 r;
    asm("mov.b64 %0, {%1, %2};" : "=l"(r) : "f"(lo), "f"(hi));
    return r;
}
__device__ __forceinline__ void upk(float& lo, float& hi, u64 v) {
    asm("mov.b64 {%0, %1}, %2;" : "=f"(lo), "=f"(hi) : "l"(v));
}
__device__ __forceinline__ u64 fma2(u64 a, u64 b, u64 c) {
    u64 d;
    asm("fma.rn.f32x2 %0, %1, %2, %3;" : "=l"(d) : "l"(a), "l"(b), "l"(c));
    return d;
}

// One MLP: inputs a_, b_ (scalar), Q = packed x-partials (5 x f32x2 = W1x-part + b1, prescaled),
// outputs O0 (control), O1, O2. tanh folded into sigmoid form with prescaled weights.
#define MLP_BODY(Q, A_, B_, O0, O1, O2) do {                                   \
    u64 aa_ = pk((A_), (A_)), bb_ = pk((B_), (B_));                            \
    float y_[10], e_[10], d_[10];                                              \
    _Pragma("unroll")                                                          \
    for (int j2 = 0; j2 < 5; ++j2) {                                           \
        u64 t1_ = fma2(U2p[j2], aa_, Q[j2]);                                   \
        u64 y2_ = fma2(U3p[j2], bb_, t1_);                                     \
        upk(y_[2*j2], y_[2*j2+1], y2_);                                        \
    }                                                                          \
    _Pragma("unroll")                                                          \
    for (int j = 0; j < 10; ++j) e_[j] = ex2_approx(y_[j]);                    \
    _Pragma("unroll")                                                          \
    for (int j = 0; j < 10; ++j) d_[j] = e_[j] + 1.0f;                         \
    u64 s2_[5];                                                                \
    _Pragma("unroll")                                                          \
    for (int j2 = 0; j2 < 5; ++j2) {                                           \
        float m_ = d_[2*j2] * d_[2*j2+1];                                      \
        float r_ = rcp_approx(m_);                                             \
        s2_[j2] = pk(d_[2*j2+1] * r_, d_[2*j2] * r_);                          \
    }                                                                          \
    u64 a0_ = fma2(V0p[0], s2_[0], C20p);                                      \
    u64 a1_ = fma2(V1p[0], s2_[0], C21p);                                      \
    u64 a2_ = fma2(V2p[0], s2_[0], C22p);                                      \
    _Pragma("unroll")                                                          \
    for (int j2 = 1; j2 < 5; ++j2) {                                           \
        a0_ = fma2(V0p[j2], s2_[j2], a0_);                                     \
        a1_ = fma2(V1p[j2], s2_[j2], a1_);                                     \
        a2_ = fma2(V2p[j2], s2_[j2], a2_);                                     \
    }                                                                          \
    float l0_, h0_, l1_, h1_, l2_, h2_;                                        \
    upk(l0_, h0_, a0_); upk(l1_, h1_, a1_); upk(l2_, h2_, a2_);                \
    (O0) = l0_ + h0_; (O1) = l1_ + h1_; (O2) = l2_ + h2_;                      \
} while (0)

__global__ __launch_bounds__(NT, 1)
void com2net_wavefront(const float* __restrict__ runs,
                       const float* __restrict__ W1,
                       const float* __restrict__ b1,
                       const float* __restrict__ W2,
                       const float* __restrict__ b2,
                       float* __restrict__ out)
{
    const int tid = threadIdx.x;
    const int r   = blockIdx.x;

    // Parity-compacted comm buffers:
    //   cA[k] = a-input (comm[2i])   for even agent i=2k
    //   cB[k] = b-input (comm[2i+3]) for odd  agent i=2k+1
    __shared__ float cA[NT + 2];
    __shared__ float cB[NT + 2];
    cA[tid] = 0.0f;
    cB[tid] = 0.0f;
    if (tid < 2) { cA[NT + tid] = 0.0f; cB[NT + tid] = 0.0f; }

    // ---- load + prescale weights; pack f32x2 pairs over hidden units (j, j+1) ----
    // tanh(z) = 2*sigma(2z) - 1 ; sigma(2z) = 1/(1 + 2^(S*z)), S = -2*log2(e)
    // layer2: out = (2*W2)@s + (b2 - W2@1)
    const float S = -2.8853900817779268f;
    u64 U0p[5], U1p[5], U2p[5], U3p[5], C1p[5];
#pragma unroll
    for (int j2 = 0; j2 < 5; ++j2) {
        int j = 2 * j2;
        U0p[j2] = pk(W1[j*4+0] * S, W1[(j+1)*4+0] * S);
        U1p[j2] = pk(W1[j*4+1] * S, W1[(j+1)*4+1] * S);
        U2p[j2] = pk(W1[j*4+2] * S, W1[(j+1)*4+2] * S);
        U3p[j2] = pk(W1[j*4+3] * S, W1[(j+1)*4+3] * S);
        C1p[j2] = pk(b1[j] * S,     b1[j+1] * S);
    }
    u64 V0p[5], V1p[5], V2p[5], C20p, C21p, C22p;
    {
        float s0 = 0.f, s1 = 0.f, s2 = 0.f;
#pragma unroll
        for (int j = 0; j < 10; ++j) {
            s0 += W2[0*10 + j]; s1 += W2[1*10 + j]; s2 += W2[2*10 + j];
        }
#pragma unroll
        for (int j2 = 0; j2 < 5; ++j2) {
            int j = 2 * j2;
            V0p[j2] = pk(2.f * W2[0*10 + j], 2.f * W2[0*10 + j + 1]);
            V1p[j2] = pk(2.f * W2[1*10 + j], 2.f * W2[1*10 + j + 1]);
            V2p[j2] = pk(2.f * W2[2*10 + j], 2.f * W2[2*10 + j + 1]);
        }
        C20p = pk(b2[0] - s0, 0.f);
        C21p = pk(b2[1] - s1, 0.f);
        C22p = pk(b2[2] - s2, 0.f);
    }

    // lane handles agents iA=2*tid, iB=2*tid+1; in phase p both at t = p - tid.
    const float* xbase = runs + (size_t)r * T_STEPS * N_AGENTS * 2 + (size_t)tid * 4;
    float*       obase = out  + (size_t)r * T_STEPS * N_AGENTS     + (size_t)tid * 2;

    // prefetch queue: xq[d] holds xs(t = p - tid + d), clamped
    float4 xq[PF];
#pragma unroll
    for (int d = 0; d < PF; ++d) {
        int tc = d - tid;
        tc = max(0, min(T_STEPS - 1, tc));
        xq[d] = *(const float4*)(xbase + (size_t)tc * (N_AGENTS * 2));
    }

    float bA = 0.0f;  // o1 of own MLP-B from previous phase

    __syncthreads();

#pragma unroll 1
    for (int p = 0; p < NPHASE; ++p) {
        // prefetch t + PF
        int tl = p - tid + PF;
        tl = max(0, min(T_STEPS - 1, tl));
        const float4 xnew = *(const float4*)(xbase + (size_t)tl * (N_AGENTS * 2));

        const int t = p - tid;
        const bool act = ((unsigned)t < (unsigned)T_STEPS);
        const float4 x = xq[0];
        xq[0] = xq[1]; xq[1] = xq[2]; xq[2] = xq[3]; xq[3] = xnew;

        // early: a-input from smem (written before last barrier)
        const float aInA = cA[tid];
        // gate b feedback: at t==0 the reference reads initial comm (0)
        const float bInA = (t >= 1) ? bA : 0.0f;

        // x-partials for BOTH MLPs up front (independent FMA work to fill MUFU shadows)
        u64 qA[5], qB[5];
        {
            u64 xx0 = pk(x.x, x.x), xx1 = pk(x.y, x.y);
            u64 xz0 = pk(x.z, x.z), xw1 = pk(x.w, x.w);
#pragma unroll
            for (int j2 = 0; j2 < 5; ++j2) {
                qA[j2] = fma2(U1p[j2], xx1, fma2(U0p[j2], xx0, C1p[j2]));
                qB[j2] = fma2(U1p[j2], xw1, fma2(U0p[j2], xz0, C1p[j2]));
            }
        }

        // ---- MLP-A (agent 2*tid at t) ----
        float o0A, o1A, aB;
        MLP_BODY(qA, aInA, bInA, o0A, o1A, aB);
        if (act && tid > 0) cB[tid - 1] = o1A;   // -> b-input of agent 2tid-1 this phase
        __syncthreads();

        // ---- MLP-B (agent 2*tid+1 at t) ----
        const float bInB = cB[tid];
        float o0B, o1B, o2B;
        MLP_BODY(qB, aB, bInB, o0B, o1B, o2B);
        cA[tid + 1] = o2B;                        // -> a-input of agent 2tid+2 next phase
        bA = o1B;
        __syncthreads();

        if (act) {
            *(float2*)(obase + (size_t)t * N_AGENTS) = make_float2(o0A, o0B);
        }
    }
}

extern "C" void kernel_launch(void* const* d_in, const int* in_sizes, int n_in,
                              void* d_out, int out_size)
{
    const float* runs = (const float*)d_in[0];
    const float* W1   = (const float*)d_in[1];
    const float* b1   = (const float*)d_in[2];
    const float* W2   = (const float*)d_in[3];
    const float* b2   = (const float*)d_in[4];
    float* out = (float*)d_out;
    com2net_wavefront<<<R_RUNS, NT>>>(runs, W1, b1, W2, b2, out);
}

// round 3
// speedup vs baseline: 1.0341x; 1.0341x over previous
#include <cuda_runtime.h>

#define R_RUNS 128
#define T_STEPS 1024
#define N_AGENTS 128
#define PF 3
#define NPHASE (T_STEPS + 31)   // 1055

typedef unsigned long long u64;

__device__ __forceinline__ float ex2_approx(float x) {
    float r;
    asm("ex2.approx.f32 %0, %1;" : "=f"(r) : "f"(x));
    return r;
}
__device__ __forceinline__ float rcp_approx(float x) {
    float r;
    asm("rcp.approx.f32 %0, %1;" : "=f"(r) : "f"(x));
    return r;
}
__device__ __forceinline__ u64 pk(float lo, float hi) {
    u64 r;
    asm("mov.b64 %0, {%1, %2};" : "=l"(r) : "f"(lo), "f"(hi));
    return r;
}
__device__ __forceinline__ void upk(float& lo, float& hi, u64 v) {
    asm("mov.b64 {%0, %1}, %2;" : "=f"(lo), "=f"(hi) : "l"(v));
}
__device__ __forceinline__ u64 fma2(u64 a, u64 b, u64 c) {
    u64 d;
    asm("fma.rn.f32x2 %0, %1, %2, %3;" : "=l"(d) : "l"(a), "l"(b), "l"(c));
    return d;
}

// One MLP. Q[5]: packed x-partials (S*(W1x@x + b1)). A_, B_: comm inputs.
// Outputs O0 (control), O1 (-> comm[2i+1]), O2 (-> comm[2i+2]).
// tanh(z) = 2/(1+2^(S z)) - 1 folded into prescaled weights.
#define MLP_BODY(Q, A_, B_, O0, O1, O2) do {                                   \
    u64 aa_ = pk((A_), (A_)), bb_ = pk((B_), (B_));                            \
    float y_[10], e_[10], d_[10];                                              \
    _Pragma("unroll")                                                          \
    for (int j2 = 0; j2 < 5; ++j2) {                                           \
        u64 t1_ = fma2(U2p[j2], aa_, Q[j2]);                                   \
        u64 y2_ = fma2(U3p[j2], bb_, t1_);                                     \
        upk(y_[2*j2], y_[2*j2+1], y2_);                                        \
    }                                                                          \
    _Pragma("unroll")                                                          \
    for (int j = 0; j < 10; ++j) e_[j] = ex2_approx(y_[j]);                    \
    _Pragma("unroll")                                                          \
    for (int j = 0; j < 10; ++j) d_[j] = e_[j] + 1.0f;                         \
    u64 s2_[5];                                                                \
    _Pragma("unroll")                                                          \
    for (int j2 = 0; j2 < 5; ++j2) {                                           \
        float m_ = d_[2*j2] * d_[2*j2+1];                                      \
        float r_ = rcp_approx(m_);                                             \
        s2_[j2] = pk(d_[2*j2+1] * r_, d_[2*j2] * r_);                          \
    }                                                                          \
    u64 a0_ = fma2(V0p[0], s2_[0], C20p);                                      \
    u64 a1_ = fma2(V1p[0], s2_[0], C21p);                                      \
    u64 a2_ = fma2(V2p[0], s2_[0], C22p);                                      \
    _Pragma("unroll")                                                          \
    for (int j2 = 1; j2 < 5; ++j2) {                                           \
        a0_ = fma2(V0p[j2], s2_[j2], a0_);                                     \
        a1_ = fma2(V1p[j2], s2_[j2], a1_);                                     \
        a2_ = fma2(V2p[j2], s2_[j2], a2_);                                     \
    }                                                                          \
    float l0_, h0_, l1_, h1_, l2_, h2_;                                        \
    upk(l0_, h0_, a0_); upk(l1_, h1_, a1_); upk(l2_, h2_, a2_);                \
    (O0) = l0_ + h0_; (O1) = l1_ + h1_; (O2) = l2_ + h2_;                      \
} while (0)

// q-partials for one slot from its (x0, x1)
#define MAKE_Q(Q, X0, X1) do {                                                 \
    u64 xx0_ = pk((X0), (X0)), xx1_ = pk((X1), (X1));                          \
    _Pragma("unroll")                                                          \
    for (int j2 = 0; j2 < 5; ++j2)                                             \
        Q[j2] = fma2(U1p[j2], xx1_, fma2(U0p[j2], xx0_, C1p[j2]));             \
} while (0)

__global__ __launch_bounds__(32, 1)
void com2net_warp(const float* __restrict__ runs,
                  const float* __restrict__ W1,
                  const float* __restrict__ b1,
                  const float* __restrict__ W2,
                  const float* __restrict__ b2,
                  float* __restrict__ out)
{
    const int k = threadIdx.x;   // lane: owns agents 4k..4k+3
    const int r = blockIdx.x;

    // ---- prescale + pack weights over hidden-unit pairs ----
    const float S = -2.8853900817779268f;   // -2*log2(e)
    u64 U0p[5], U1p[5], U2p[5], U3p[5], C1p[5];
#pragma unroll
    for (int j2 = 0; j2 < 5; ++j2) {
        int j = 2 * j2;
        U0p[j2] = pk(W1[j*4+0] * S, W1[(j+1)*4+0] * S);
        U1p[j2] = pk(W1[j*4+1] * S, W1[(j+1)*4+1] * S);
        U2p[j2] = pk(W1[j*4+2] * S, W1[(j+1)*4+2] * S);
        U3p[j2] = pk(W1[j*4+3] * S, W1[(j+1)*4+3] * S);
        C1p[j2] = pk(b1[j] * S,     b1[j+1] * S);
    }
    u64 V0p[5], V1p[5], V2p[5], C20p, C21p, C22p;
    {
        float s0 = 0.f, s1 = 0.f, s2 = 0.f;
#pragma unroll
        for (int j = 0; j < 10; ++j) {
            s0 += W2[0*10 + j]; s1 += W2[1*10 + j]; s2 += W2[2*10 + j];
        }
#pragma unroll
        for (int j2 = 0; j2 < 5; ++j2) {
            int j = 2 * j2;
            V0p[j2] = pk(2.f * W2[0*10 + j], 2.f * W2[0*10 + j + 1]);
            V1p[j2] = pk(2.f * W2[1*10 + j], 2.f * W2[1*10 + j + 1]);
            V2p[j2] = pk(2.f * W2[2*10 + j], 2.f * W2[2*10 + j + 1]);
        }
        C20p = pk(b2[0] - s0, 0.f);
        C21p = pk(b2[1] - s1, 0.f);
        C22p = pk(b2[2] - s2, 0.f);
    }

    // x layout: runs[r, t, i, 0:2]; lane reads 8 contiguous floats (agents 4k..4k+3)
    const float* xbase = runs + (size_t)r * T_STEPS * N_AGENTS * 2 + (size_t)k * 8;
    float*       obase = out  + (size_t)r * T_STEPS * N_AGENTS     + (size_t)k * 4;

    // prefetch queue: (xa, xb)[d] = xs at t = p - k + d (clamped)
    float4 xa[PF], xb[PF];
#pragma unroll
    for (int d = 0; d < PF; ++d) {
        int tc = d - k;
        tc = max(0, min(T_STEPS - 1, tc));
        const float* a = xbase + (size_t)tc * (N_AGENTS * 2);
        xa[d] = *(const float4*)a;
        xb[d] = *(const float4*)(a + 4);
    }

    // cross-phase registers
    float o1p1 = 0.f, o1p2 = 0.f, o1p3 = 0.f;  // o1 of slots 1..3, prev phase
    float o2s3p = 0.f;                          // own slot-3 o2, prev phase

#pragma unroll 1
    for (int p = 0; p < NPHASE; ++p) {
        const int t = p - k;
        const bool act = ((unsigned)t < (unsigned)T_STEPS);
        const bool tv1 = (t >= 1);

        // a-chain: lane k-1's slot-3 o2 from prev phase (same t)
        const float aUp  = __shfl_up_sync(0xffffffffu, o2s3p, 1);
        const float aIn0 = (k == 0) ? 0.f : aUp;

        // prefetch t + PF
        int tl = p - k + PF;
        tl = max(0, min(T_STEPS - 1, tl));
        const float* la = xbase + (size_t)tl * (N_AGENTS * 2);
        const float4 na = *(const float4*)la;
        const float4 nb = *(const float4*)(la + 4);

        const float4 x01 = xa[0], x23 = xb[0];
#pragma unroll
        for (int d = 0; d < PF - 1; ++d) { xa[d] = xa[d + 1]; xb[d] = xb[d + 1]; }
        xa[PF - 1] = na; xb[PF - 1] = nb;

        // ---- slot 0 : agent 4k ----
        u64 q0[5]; MAKE_Q(q0, x01.x, x01.y);
        const float b0 = tv1 ? o1p1 : 0.f;
        float o00, o01, o02;
        MLP_BODY(q0, aIn0, b0, o00, o01, o02);

        // b-chain: lane k+1's slot-0 o1 (its t = our t-1), same phase
        const float bDn = __shfl_down_sync(0xffffffffu, o01, 1);

        // ---- slot 1 : agent 4k+1 ----
        u64 q1[5]; MAKE_Q(q1, x01.z, x01.w);
        const float b1i = tv1 ? o1p2 : 0.f;
        float o10, o11, o12;
        MLP_BODY(q1, o02, b1i, o10, o11, o12);

        // ---- slot 2 : agent 4k+2 ----
        u64 q2[5]; MAKE_Q(q2, x23.x, x23.y);
        const float b2i = tv1 ? o1p3 : 0.f;
        float o20, o21, o22;
        MLP_BODY(q2, o12, b2i, o20, o21, o22);

        // ---- slot 3 : agent 4k+3 ----
        u64 q3[5]; MAKE_Q(q3, x23.z, x23.w);
        const float b3i = (tv1 && k < 31) ? bDn : 0.f;
        float o30, o31, o32;
        MLP_BODY(q3, o22, b3i, o30, o31, o32);

        // roll cross-phase state
        o1p1 = o11; o1p2 = o21; o1p3 = o31; o2s3p = o32;

        if (act) {
            *(float4*)(obase + (size_t)t * N_AGENTS) = make_float4(o00, o10, o20, o30);
        }
    }
}

extern "C" void kernel_launch(void* const* d_in, const int* in_sizes, int n_in,
                              void* d_out, int out_size)
{
    const float* runs = (const float*)d_in[0];
    const float* W1   = (const float*)d_in[1];
    const float* b1   = (const float*)d_in[2];
    const float* W2   = (const float*)d_in[3];
    const float* b2   = (const float*)d_in[4];
    float* out = (float*)d_out;
    com2net_warp<<<R_RUNS, 32>>>(runs, W1, b1, W2, b2, out);
}

// round 4
// speedup vs baseline: 1.0525x; 1.0179x over previous
#include <cuda_runtime.h>

#define R_RUNS 128
#define T_STEPS 1024
#define N_AGENTS 128
#define NT 64                 // 2 warps, lane k=tid owns agents 2k, 2k+1
#define PF 3
#define NPHASE 1087           // p = t + k, k in [0,63], t in [0,1024)

typedef unsigned long long u64;

__device__ __forceinline__ float tanh_approx(float x) {
    float r;
    asm("tanh.approx.f32 %0, %1;" : "=f"(r) : "f"(x));
    return r;
}
__device__ __forceinline__ u64 pk(float lo, float hi) {
    u64 r;
    asm("mov.b64 %0, {%1, %2};" : "=l"(r) : "f"(lo), "f"(hi));
    return r;
}
__device__ __forceinline__ void upk(float& lo, float& hi, u64 v) {
    asm("mov.b64 {%0, %1}, %2;" : "=f"(lo), "=f"(hi) : "l"(v));
}
__device__ __forceinline__ u64 fma2(u64 a, u64 b, u64 c) {
    u64 d;
    asm("fma.rn.f32x2 %0, %1, %2, %3;" : "=l"(d) : "l"(a), "l"(b), "l"(c));
    return d;
}

// tagged 8B slot: {tag:32 | value:32} in one volatile 64-bit access
__device__ __forceinline__ void slot_write(volatile u64* s, float v, int tag) {
    *s = ((u64)(unsigned)tag << 32) | (u64)__float_as_uint(v);
}
__device__ __forceinline__ float slot_poll(volatile u64* s, int tag) {
    u64 v;
    do { v = *s; } while ((int)(unsigned)(v >> 32) != tag);
    return __uint_as_float((unsigned)v);
}

// MLP: tanh hidden layer. Q[5] = packed x-partials (W1x@x + b1). A_,B_ comm inputs.
#define MLP_BODY(Q, A_, B_, O0, O1, O2) do {                                   \
    u64 aa_ = pk((A_), (A_)), bb_ = pk((B_), (B_));                            \
    float y_[10], h_[10];                                                      \
    _Pragma("unroll")                                                          \
    for (int j2 = 0; j2 < 5; ++j2) {                                           \
        u64 y2_ = fma2(U3p[j2], bb_, fma2(U2p[j2], aa_, Q[j2]));               \
        upk(y_[2*j2], y_[2*j2+1], y2_);                                        \
    }                                                                          \
    _Pragma("unroll")                                                          \
    for (int j = 0; j < 10; ++j) h_[j] = tanh_approx(y_[j]);                   \
    u64 s2_[5];                                                                \
    _Pragma("unroll")                                                          \
    for (int j2 = 0; j2 < 5; ++j2) s2_[j2] = pk(h_[2*j2], h_[2*j2+1]);         \
    u64 a0_ = fma2(V0p[0], s2_[0], C20p);                                      \
    u64 a1_ = fma2(V1p[0], s2_[0], C21p);                                      \
    u64 a2_ = fma2(V2p[0], s2_[0], C22p);                                      \
    _Pragma("unroll")                                                          \
    for (int j2 = 1; j2 < 5; ++j2) {                                           \
        a0_ = fma2(V0p[j2], s2_[j2], a0_);                                     \
        a1_ = fma2(V1p[j2], s2_[j2], a1_);                                     \
        a2_ = fma2(V2p[j2], s2_[j2], a2_);                                     \
    }                                                                          \
    float l0_, h0_, l1_, h1_, l2_, h2_;                                        \
    upk(l0_, h0_, a0_); upk(l1_, h1_, a1_); upk(l2_, h2_, a2_);                \
    (O0) = l0_ + h0_; (O1) = l1_ + h1_; (O2) = l2_ + h2_;                      \
} while (0)

#define MAKE_Q(Q, X0, X1) do {                                                 \
    u64 xx0_ = pk((X0), (X0)), xx1_ = pk((X1), (X1));                          \
    _Pragma("unroll")                                                          \
    for (int j2 = 0; j2 < 5; ++j2)                                             \
        Q[j2] = fma2(U1p[j2], xx1_, fma2(U0p[j2], xx0_, C1p[j2]));             \
} while (0)

__global__ __launch_bounds__(NT, 1)
void com2net_2w(const float* __restrict__ runs,
                const float* __restrict__ W1,
                const float* __restrict__ b1,
                const float* __restrict__ W2,
                const float* __restrict__ b2,
                float* __restrict__ out)
{
    const int k = threadIdx.x;        // pair index 0..63
    const int l = k & 31;             // lane in warp
    const int w = k >> 5;             // warp 0 | 1

    // boundary slots: slot1 = w1.lane0 o1A (same phase) -> w0.lane31 B
    //                 slot2 = w0.lane31 o2B (phase p)   -> w1.lane0 A at p+1
    __shared__ u64 slot1, slot2;
    if (k == 0) {
        slot1 = ((u64)(unsigned)(-1) << 32);
        slot2 = ((u64)(unsigned)(-1) << 32);
    }
    __syncthreads();   // once, at start

    // ---- pack weights over hidden-unit pairs (no prescale; tanh direct) ----
    u64 U0p[5], U1p[5], U2p[5], U3p[5], C1p[5];
#pragma unroll
    for (int j2 = 0; j2 < 5; ++j2) {
        int j = 2 * j2;
        U0p[j2] = pk(W1[j*4+0], W1[(j+1)*4+0]);
        U1p[j2] = pk(W1[j*4+1], W1[(j+1)*4+1]);
        U2p[j2] = pk(W1[j*4+2], W1[(j+1)*4+2]);
        U3p[j2] = pk(W1[j*4+3], W1[(j+1)*4+3]);
        C1p[j2] = pk(b1[j],     b1[j+1]);
    }
    u64 V0p[5], V1p[5], V2p[5], C20p, C21p, C22p;
#pragma unroll
    for (int j2 = 0; j2 < 5; ++j2) {
        int j = 2 * j2;
        V0p[j2] = pk(W2[0*10+j], W2[0*10+j+1]);
        V1p[j2] = pk(W2[1*10+j], W2[1*10+j+1]);
        V2p[j2] = pk(W2[2*10+j], W2[2*10+j+1]);
    }
    C20p = pk(b2[0], 0.f);
    C21p = pk(b2[1], 0.f);
    C22p = pk(b2[2], 0.f);

    const int r = blockIdx.x;
    const float* xbase = runs + (size_t)r * T_STEPS * N_AGENTS * 2 + (size_t)k * 4;
    float*       obase = out  + (size_t)r * T_STEPS * N_AGENTS     + (size_t)k * 2;

    // prefetch queue: xq[d] = x at t = p - k + d (clamped)
    float4 xq[PF];
#pragma unroll
    for (int d = 0; d < PF; ++d) {
        int tc = d - k;
        tc = max(0, min(T_STEPS - 1, tc));
        xq[d] = *(const float4*)(xbase + (size_t)tc * (N_AGENTS * 2));
    }

    float bA    = 0.f;   // own MLP-B o1 from prev phase -> A's b-input (t-1)
    float o2Bpv = 0.f;   // own MLP-B o2 from prev phase -> neighbor's A a-input

#pragma unroll 1
    for (int p = 0; p < NPHASE; ++p) {
        const int t = p - k;
        const bool act = ((unsigned)t < (unsigned)T_STEPS);
        const bool tv1 = (t >= 1);

        // prefetch t + PF
        int tl = p - k + PF;
        tl = max(0, min(T_STEPS - 1, tl));
        const float4 xnew = *(const float4*)(xbase + (size_t)tl * (N_AGENTS * 2));
        const float4 x = xq[0];
#pragma unroll
        for (int d = 0; d < PF - 1; ++d) xq[d] = xq[d + 1];
        xq[PF - 1] = xnew;

        // x-partials for both MLPs up front (independent work)
        u64 qA[5], qB[5];
        MAKE_Q(qA, x.x, x.y);
        MAKE_Q(qB, x.z, x.w);

        // a-input of A: pair k-1's o2B (same t, prev phase). in-warp: shfl_up.
        const float aUp = __shfl_up_sync(0xffffffffu, o2Bpv, 1);
        float aInA;
        if (w == 1) {
            const float s2v = slot_poll(&slot2, p - 1);   // warp-uniform poll
            aInA = (l == 0) ? s2v : aUp;
        } else {
            aInA = (l == 0) ? 0.f : aUp;                  // comm[0] is never written
        }
        const float bInA = tv1 ? bA : 0.f;

        // ---- MLP-A (agent 2k, t) ----
        float o0A, o1A, o2A;
        MLP_BODY(qA, aInA, bInA, o0A, o1A, o2A);

        if (w == 1 && l == 0) slot_write(&slot1, o1A, p);
        const float bDn = __shfl_down_sync(0xffffffffu, o1A, 1);

        // b-input of B: pair k+1's o1A (same phase, its t-1).
        float bInB;
        if (w == 0) {
            const float s1v = slot_poll(&slot1, p);       // warp-uniform poll
            bInB = (l == 31) ? s1v : bDn;
        } else {
            bInB = (l == 31) ? 0.f : bDn;                 // comm[257] is never written
        }
        bInB = tv1 ? bInB : 0.f;

        // ---- MLP-B (agent 2k+1, t); a-input = own o2A (same t) ----
        float o0B, o1B, o2B;
        MLP_BODY(qB, o2A, bInB, o0B, o1B, o2B);

        if (w == 0 && l == 31) slot_write(&slot2, o2B, p);

        bA = o1B;
        o2Bpv = o2B;

        if (act) {
            *(float2*)(obase + (size_t)t * N_AGENTS) = make_float2(o0A, o0B);
        }
    }
}

extern "C" void kernel_launch(void* const* d_in, const int* in_sizes, int n_in,
                              void* d_out, int out_size)
{
    const float* runs = (const float*)d_in[0];
    const float* W1   = (const float*)d_in[1];
    const float* b1   = (const float*)d_in[2];
    const float* W2   = (const float*)d_in[3];
    const float* b2   = (const float*)d_in[4];
    float* out = (float*)d_out;
    com2net_2w<<<R_RUNS, NT>>>(runs, W1, b1, W2, b2, out);
}

// round 5
// speedup vs baseline: 1.3324x; 1.2659x over previous
#include <cuda_runtime.h>

#define R_RUNS 128
#define T_STEPS 1024
#define N_AGENTS 128
#define PF 3
#define NPHASE 1087   // pair j in [0,127]... lane k owns pairs 2k,2k+1; p up to 63+1023

typedef unsigned long long u64;

__device__ __forceinline__ float tanh_approx(float x) {
    float r;
    asm("tanh.approx.f32 %0, %1;" : "=f"(r) : "f"(x));
    return r;
}
__device__ __forceinline__ u64 pk(float lo, float hi) {
    u64 r;
    asm("mov.b64 %0, {%1, %2};" : "=l"(r) : "f"(lo), "f"(hi));
    return r;
}
__device__ __forceinline__ void upk(float& lo, float& hi, u64 v) {
    asm("mov.b64 {%0, %1}, %2;" : "=f"(lo), "=f"(hi) : "l"(v));
}
__device__ __forceinline__ u64 fma2(u64 a, u64 b, u64 c) {
    u64 d;
    asm("fma.rn.f32x2 %0, %1, %2, %3;" : "=l"(d) : "l"(a), "l"(b), "l"(c));
    return d;
}

// MLP with tanh hidden layer. Q[5]: packed x-partials (W1x@x + b1).
#define MLP_BODY(Q, A_, B_, O0, O1, O2) do {                                   \
    u64 aa_ = pk((A_), (A_)), bb_ = pk((B_), (B_));                            \
    float y_[10], h_[10];                                                      \
    _Pragma("unroll")                                                          \
    for (int j2 = 0; j2 < 5; ++j2) {                                           \
        u64 y2_ = fma2(U3p[j2], bb_, fma2(U2p[j2], aa_, Q[j2]));               \
        upk(y_[2*j2], y_[2*j2+1], y2_);                                        \
    }                                                                          \
    _Pragma("unroll")                                                          \
    for (int j = 0; j < 10; ++j) h_[j] = tanh_approx(y_[j]);                   \
    u64 s2_[5];                                                                \
    _Pragma("unroll")                                                          \
    for (int j2 = 0; j2 < 5; ++j2) s2_[j2] = pk(h_[2*j2], h_[2*j2+1]);         \
    u64 a0_ = fma2(V0p[0], s2_[0], C20p);                                      \
    u64 a1_ = fma2(V1p[0], s2_[0], C21p);                                      \
    u64 a2_ = fma2(V2p[0], s2_[0], C22p);                                      \
    _Pragma("unroll")                                                          \
    for (int j2 = 1; j2 < 5; ++j2) {                                           \
        a0_ = fma2(V0p[j2], s2_[j2], a0_);                                     \
        a1_ = fma2(V1p[j2], s2_[j2], a1_);                                     \
        a2_ = fma2(V2p[j2], s2_[j2], a2_);                                     \
    }                                                                          \
    float l0_, h0_, l1_, h1_, l2_, h2_;                                        \
    upk(l0_, h0_, a0_); upk(l1_, h1_, a1_); upk(l2_, h2_, a2_);                \
    (O0) = l0_ + h0_; (O1) = l1_ + h1_; (O2) = l2_ + h2_;                      \
} while (0)

#define MAKE_Q(Q, X0, X1) do {                                                 \
    u64 xx0_ = pk((X0), (X0)), xx1_ = pk((X1), (X1));                          \
    _Pragma("unroll")                                                          \
    for (int j2 = 0; j2 < 5; ++j2)                                             \
        Q[j2] = fma2(U1p[j2], xx1_, fma2(U0p[j2], xx0_, C1p[j2]));             \
} while (0)

__global__ __launch_bounds__(32, 1)
void com2net_1w(const float* __restrict__ runs,
                const float* __restrict__ W1,
                const float* __restrict__ b1,
                const float* __restrict__ W2,
                const float* __restrict__ b2,
                float* __restrict__ out)
{
    const int k = threadIdx.x;   // lane owns pairs 2k (agents 4k,4k+1 @ t0) and 2k+1 (agents 4k+2,4k+3 @ t0-1)
    const int r = blockIdx.x;

    // ---- pack weights over hidden-unit pairs ----
    u64 U0p[5], U1p[5], U2p[5], U3p[5], C1p[5];
#pragma unroll
    for (int j2 = 0; j2 < 5; ++j2) {
        int j = 2 * j2;
        U0p[j2] = pk(W1[j*4+0], W1[(j+1)*4+0]);
        U1p[j2] = pk(W1[j*4+1], W1[(j+1)*4+1]);
        U2p[j2] = pk(W1[j*4+2], W1[(j+1)*4+2]);
        U3p[j2] = pk(W1[j*4+3], W1[(j+1)*4+3]);
        C1p[j2] = pk(b1[j],     b1[j+1]);
    }
    u64 V0p[5], V1p[5], V2p[5], C20p, C21p, C22p;
#pragma unroll
    for (int j2 = 0; j2 < 5; ++j2) {
        int j = 2 * j2;
        V0p[j2] = pk(W2[0*10+j], W2[0*10+j+1]);
        V1p[j2] = pk(W2[1*10+j], W2[1*10+j+1]);
        V2p[j2] = pk(W2[2*10+j], W2[2*10+j+1]);
    }
    C20p = pk(b2[0], 0.f);
    C21p = pk(b2[1], 0.f);
    C22p = pk(b2[2], 0.f);

    // x pointers: pair0 -> agents 4k..4k+1 (8k floats in), pair1 -> agents 4k+2..4k+3
    const float* xb0 = runs + (size_t)r * T_STEPS * N_AGENTS * 2 + (size_t)k * 8;
    const float* xb1 = xb0 + 4;
    float*       ob  = out  + (size_t)r * T_STEPS * N_AGENTS;

    // prefetch queues: xq0[d] = x(t0 = p-2k+d), xq1[d] = x(t1 = t0-1+d... same shift)
    float4 xq0[PF], xq1[PF];
#pragma unroll
    for (int d = 0; d < PF; ++d) {
        int t0c = d - 2 * k;       t0c = max(0, min(T_STEPS - 1, t0c));
        int t1c = d - 2 * k - 1;   t1c = max(0, min(T_STEPS - 1, t1c));
        xq0[d] = *(const float4*)(xb0 + (size_t)t0c * (N_AGENTS * 2));
        xq1[d] = *(const float4*)(xb1 + (size_t)t1c * (N_AGENTS * 2));
    }

    // loop-carried state (per lane): o1/o2 of both B MLPs from previous phase
    float o1B0 = 0.f, o2B0 = 0.f, o1B1 = 0.f, o2B1 = 0.f;

#pragma unroll 1
    for (int p = 0; p < NPHASE; ++p) {
        const int t0 = p - 2 * k;        // pair 2k timestep
        const int t1 = t0 - 1;           // pair 2k+1 timestep
        const bool act0 = ((unsigned)t0 < (unsigned)T_STEPS);
        const bool act1 = ((unsigned)t1 < (unsigned)T_STEPS);

        // a-input for A0: lane k-1's B1.o2 from prev phase (same t0)
        const float aUp = __shfl_up_sync(0xffffffffu, o2B1, 1);

        // prefetch t + PF
        {
            int t0c = t0 + PF;     t0c = max(0, min(T_STEPS - 1, t0c));
            int t1c = t1 + PF;     t1c = max(0, min(T_STEPS - 1, t1c));
            const float4 n0 = *(const float4*)(xb0 + (size_t)t0c * (N_AGENTS * 2));
            const float4 n1 = *(const float4*)(xb1 + (size_t)t1c * (N_AGENTS * 2));
            // rotate after reading head below
            float4 h0 = xq0[0], h1 = xq1[0];
#pragma unroll
            for (int d = 0; d < PF - 1; ++d) { xq0[d] = xq0[d + 1]; xq1[d] = xq1[d + 1]; }
            xq0[PF - 1] = n0; xq1[PF - 1] = n1;
            xq0[0] = xq0[0]; // no-op
            // stash heads in local names via shadowing trick below
            // (we just use h0/h1 directly)
            // ---- x-partials for all 4 MLPs ----
            u64 q0a[5], q0b[5], q1a[5], q1b[5];
            MAKE_Q(q0a, h0.x, h0.y);
            MAKE_Q(q0b, h0.z, h0.w);
            MAKE_Q(q1a, h1.x, h1.y);
            MAKE_Q(q1b, h1.z, h1.w);

            // ---- A-stage: two independent MLPs ----
            const float aA0 = (k == 0) ? 0.f : aUp;         // comm[0] never written
            const float bA0 = (t0 >= 1) ? o1B0 : 0.f;
            const float aA1 = o2B0;                          // own B0.o2 prev phase (t1)
            const float bA1 = (t1 >= 1) ? o1B1 : 0.f;

            float o0A0, o1A0, o2A0, o0A1, o1A1, o2A1;
            MLP_BODY(q0a, aA0, bA0, o0A0, o1A0, o2A0);
            MLP_BODY(q1a, aA1, bA1, o0A1, o1A1, o2A1);

            // b-input for B1: lane k+1's A0.o1 (this phase, its t0 = our t1-1)
            const float bDn = __shfl_down_sync(0xffffffffu, o1A0, 1);

            // ---- B-stage: two independent MLPs ----
            const float bB0 = (t0 >= 1) ? o1A1 : 0.f;        // own A1.o1 (t0-1)
            const float bB1 = (t1 >= 1) ? ((k == 31) ? 0.f : bDn) : 0.f;  // comm[257] never written

            float o0B0, n_o1B0, n_o2B0, o0B1, n_o1B1, n_o2B1;
            MLP_BODY(q0b, o2A0, bB0, o0B0, n_o1B0, n_o2B0);
            MLP_BODY(q1b, o2A1, bB1, o0B1, n_o1B1, n_o2B1);

            o1B0 = n_o1B0; o2B0 = n_o2B0;
            o1B1 = n_o1B1; o2B1 = n_o2B1;

            // ---- outputs: controls (o0) of the 4 agents ----
            if (act0) *(float2*)(ob + (size_t)t0 * N_AGENTS + 4 * k)     = make_float2(o0A0, o0B0);
            if (act1) *(float2*)(ob + (size_t)t1 * N_AGENTS + 4 * k + 2) = make_float2(o0A1, o0B1);
        }
    }
}

extern "C" void kernel_launch(void* const* d_in, const int* in_sizes, int n_in,
                              void* d_out, int out_size)
{
    const float* runs = (const float*)d_in[0];
    const float* W1   = (const float*)d_in[1];
    const float* b1   = (const float*)d_in[2];
    const float* W2   = (const float*)d_in[3];
    const float* b2   = (const float*)d_in[4];
    float* out = (float*)d_out;
    com2net_1w<<<R_RUNS, 32>>>(runs, W1, b1, W2, b2, out);
}